// round 13
// baseline (speedup 1.0000x reference)
#include <cuda_runtime.h>
#include <cuda_bf16.h>
#include <math.h>

#define N_NODES 50000
#define N_EDGES 800000
#define H       64
#define L_LAYERS 14
#define IN_DIM  128
#define OUT_DIM 112
#define MSG_EPS 1e-7f
#define LN_EPS  1e-5f

// ---------------- scratch (device globals: no allocations allowed) ----------
__device__ float g_h[N_NODES * H];     // node state (residual carry)
__device__ float g_msg[N_NODES * H];   // message source h2 = relu(LN(h)) (or relu(h_enc) for layer 0)
__device__ float g_agg[N_NODES * H];   // softmax aggregation result
__device__ int   g_rowptr[N_NODES + 1];
__device__ int   g_cursor[N_NODES];
__device__ int   g_csrc[N_EDGES];
__device__ int   g_is32;               // 1 if edge_index is int32, 0 if int64

// ---------------- dtype detection -------------------------------------------
// Sample the first 1024 entries under the int64 interpretation (byte offsets
// < 8KB: in-bounds for either dtype). If any value falls outside [0, N_NODES)
// the buffer must really be int32: an int64-interpreted pair is lo + hi*2^32
// with hi uniform in [0, 50000), so hi==0 for all 1024 samples has probability
// ~(1/50000)^1024 ~= 0. Deterministic: pure function of the input bytes.
__global__ void detect_kernel(const void* __restrict__ ei) {
    if (threadIdx.x == 0 && blockIdx.x == 0) {
        const long long* p = (const long long*)ei;
        int bad = 0;
        for (int i = 0; i < 1024; i++) {
            long long v = p[i];
            if (v < 0 || v >= N_NODES) { bad = 1; break; }
        }
        g_is32 = bad;
    }
}

__device__ __forceinline__ int load_idx(const void* ei, int i, int is32) {
    int v = is32 ? ((const int*)ei)[i] : (int)((const long long*)ei)[i];
    // defensive clamp (no-op for valid data; prevents address-space traps)
    v = v < 0 ? 0 : (v >= N_NODES ? N_NODES - 1 : v);
    return v;
}

// ---------------- CSR build --------------------------------------------------
__global__ void zero_kernel() {
    int i = blockIdx.x * blockDim.x + threadIdx.x;
    if (i < N_NODES) g_cursor[i] = 0;
}

__global__ void count_kernel(const void* __restrict__ ei) {
    int e = blockIdx.x * blockDim.x + threadIdx.x;
    if (e < N_EDGES) {
        int is32 = g_is32;
        int d = load_idx(ei, N_EDGES + e, is32);
        atomicAdd(&g_cursor[d], 1);
    }
}

__global__ void scan_kernel() {
    __shared__ int sm[1024];
    int t = threadIdx.x;
    const int CH = (N_NODES + 1023) / 1024;
    int base = t * CH;
    int lim = base + CH; if (lim > N_NODES) lim = N_NODES;
    int loc = 0;
    for (int i = base; i < lim; i++) loc += g_cursor[i];
    sm[t] = loc;
    __syncthreads();
    for (int o = 1; o < 1024; o <<= 1) {
        int v = (t >= o) ? sm[t - o] : 0;
        __syncthreads();
        sm[t] += v;
        __syncthreads();
    }
    int run = sm[t] - loc;  // exclusive prefix
    for (int i = base; i < lim; i++) {
        int c = g_cursor[i];
        g_rowptr[i] = run;
        g_cursor[i] = run;
        run += c;
    }
    if (t == 1023) g_rowptr[N_NODES] = sm[1023];
}

__global__ void scatter_kernel(const void* __restrict__ ei) {
    int e = blockIdx.x * blockDim.x + threadIdx.x;
    if (e < N_EDGES) {
        int is32 = g_is32;
        int s = load_idx(ei, e, is32);
        int d = load_idx(ei, N_EDGES + e, is32);
        int p = atomicAdd(&g_cursor[d], 1);
        g_csrc[p] = s;
    }
}

// per-row insertion sort: makes CSR (and thus fp sum order) deterministic
__global__ void sort_kernel() {
    int n = blockIdx.x * blockDim.x + threadIdx.x;
    if (n >= N_NODES) return;
    int s = g_rowptr[n], e = g_rowptr[n + 1];
    for (int i = s + 1; i < e; i++) {
        int v = g_csrc[i];
        int j = i - 1;
        while (j >= s && g_csrc[j] > v) { g_csrc[j + 1] = g_csrc[j]; j--; }
        g_csrc[j + 1] = v;
    }
}

// ---------------- encoder: h = x @ enc_W + enc_b ; msg = relu(h) -------------
__global__ __launch_bounds__(256) void enc_kernel(const float* __restrict__ x,
                                                  const float* __restrict__ W,
                                                  const float* __restrict__ b) {
    __shared__ __align__(16) float2 Ws[IN_DIM][H / 2];  // Ws[k][t] = (W[k][t], W[k][t+32])
    __shared__ __align__(16) float  sin_[8][IN_DIM];
    int t = threadIdx.x & 31;
    int w = threadIdx.x >> 5;

    for (int i = threadIdx.x; i < IN_DIM * (H / 2); i += blockDim.x) {
        int k = i >> 5, tt = i & 31;
        Ws[k][tt] = make_float2(W[k * H + tt], W[k * H + tt + 32]);
    }
    __syncthreads();

    float bb0 = b[t], bb1 = b[t + 32];
    int nwarps = gridDim.x * (blockDim.x >> 5);
    for (int row = blockIdx.x * 8 + w; row < N_NODES; row += nwarps) {
        const float4* xr = (const float4*)(x + (size_t)row * IN_DIM);
        ((float4*)sin_[w])[t] = xr[t];         // 32 lanes x 16B = 128 floats
        __syncwarp();
        float a0 = bb0, a1 = bb1;
#pragma unroll 16
        for (int k = 0; k < IN_DIM; k++) {
            float a = sin_[w][k];
            float2 wk = Ws[k][t];
            a0 = fmaf(a, wk.x, a0);
            a1 = fmaf(a, wk.y, a1);
        }
        g_h[row * H + t] = a0;
        g_h[row * H + t + 32] = a1;
        g_msg[row * H + t] = fmaxf(a0, 0.f);
        g_msg[row * H + t + 32] = fmaxf(a1, 0.f);
        __syncwarp();
    }
}

// ---------------- softmax aggregation (no-max-pass; values bounded by LN) ----
// warp per node; lane t handles features (2t, 2t+1) as a float2
__global__ __launch_bounds__(512) void agg_kernel() {
    int node = blockIdx.x * 16 + (threadIdx.x >> 5);
    if (node >= N_NODES) return;
    int t = threadIdx.x & 31;
    int s = g_rowptr[node], e = g_rowptr[node + 1];

    float d0 = 0.f, d1 = 0.f, n0 = 0.f, n1 = 0.f;
#define PROC(p) { float vx = (p).x + MSG_EPS; float vy = (p).y + MSG_EPS; \
                  float wx = __expf(vx); float wy = __expf(vy); \
                  d0 += wx; n0 = fmaf(vx, wx, n0); \
                  d1 += wy; n1 = fmaf(vy, wy, n1); }
    int i = s;
    for (; i + 8 <= e; i += 8) {
        int s0 = __ldg(&g_csrc[i]);
        int s1 = __ldg(&g_csrc[i + 1]);
        int s2 = __ldg(&g_csrc[i + 2]);
        int s3 = __ldg(&g_csrc[i + 3]);
        int s4 = __ldg(&g_csrc[i + 4]);
        int s5 = __ldg(&g_csrc[i + 5]);
        int s6 = __ldg(&g_csrc[i + 6]);
        int s7 = __ldg(&g_csrc[i + 7]);
        float2 v0 = __ldg((const float2*)&g_msg[s0 * H + 2 * t]);
        float2 v1 = __ldg((const float2*)&g_msg[s1 * H + 2 * t]);
        float2 v2 = __ldg((const float2*)&g_msg[s2 * H + 2 * t]);
        float2 v3 = __ldg((const float2*)&g_msg[s3 * H + 2 * t]);
        float2 v4 = __ldg((const float2*)&g_msg[s4 * H + 2 * t]);
        float2 v5 = __ldg((const float2*)&g_msg[s5 * H + 2 * t]);
        float2 v6 = __ldg((const float2*)&g_msg[s6 * H + 2 * t]);
        float2 v7 = __ldg((const float2*)&g_msg[s7 * H + 2 * t]);
        PROC(v0); PROC(v1); PROC(v2); PROC(v3);
        PROC(v4); PROC(v5); PROC(v6); PROC(v7);
    }
    for (; i + 4 <= e; i += 4) {
        int s0 = __ldg(&g_csrc[i]);
        int s1 = __ldg(&g_csrc[i + 1]);
        int s2 = __ldg(&g_csrc[i + 2]);
        int s3 = __ldg(&g_csrc[i + 3]);
        float2 v0 = __ldg((const float2*)&g_msg[s0 * H + 2 * t]);
        float2 v1 = __ldg((const float2*)&g_msg[s1 * H + 2 * t]);
        float2 v2 = __ldg((const float2*)&g_msg[s2 * H + 2 * t]);
        float2 v3 = __ldg((const float2*)&g_msg[s3 * H + 2 * t]);
        PROC(v0); PROC(v1); PROC(v2); PROC(v3);
    }
    for (; i < e; i++) {
        int s0 = __ldg(&g_csrc[i]);
        float2 v0 = __ldg((const float2*)&g_msg[s0 * H + 2 * t]);
        PROC(v0);
    }
#undef PROC
    float2 out;
    out.x = (e > s) ? n0 / d0 : 0.f;
    out.y = (e > s) ? n1 / d1 : 0.f;
    *(float2*)&g_agg[node * H + 2 * t] = out;
}

// ---------------- fused linear (+bias, +residual) and next-layer LN+ReLU -----
// warp per row; lane t owns outputs t and t+32
__global__ __launch_bounds__(256) void lin_kernel(const float* __restrict__ W,
                                                  const float* __restrict__ bias,
                                                  int use_msg_as_lin, int has_res,
                                                  int ln_layer,
                                                  const float* __restrict__ ln_g,
                                                  const float* __restrict__ ln_b) {
    __shared__ __align__(16) float2 Ws[H][H / 2];
    __shared__ __align__(16) float  sin_[8][H];
    int t = threadIdx.x & 31;
    int w = threadIdx.x >> 5;

    for (int i = threadIdx.x; i < H * (H / 2); i += blockDim.x) {
        int k = i >> 5, tt = i & 31;
        Ws[k][tt] = make_float2(W[k * H + tt], W[k * H + tt + 32]);
    }
    __syncthreads();

    float bb0 = bias[t], bb1 = bias[t + 32];
    float g0 = 1.f, g1 = 1.f, be0 = 0.f, be1 = 0.f;
    if (ln_layer >= 0) {
        g0 = ln_g[ln_layer * H + t];      g1 = ln_g[ln_layer * H + t + 32];
        be0 = ln_b[ln_layer * H + t];     be1 = ln_b[ln_layer * H + t + 32];
    }

    const float* lin = use_msg_as_lin ? g_msg : g_h;
    int nwarps = gridDim.x * (blockDim.x >> 5);
    for (int row = blockIdx.x * 8 + w; row < N_NODES; row += nwarps) {
        int base = row * H;
        float i0 = lin[base + t] + g_agg[base + t];
        float i1 = lin[base + t + 32] + g_agg[base + t + 32];
        sin_[w][t] = i0;
        sin_[w][t + 32] = i1;
        __syncwarp();
        float a0 = bb0, a1 = bb1;
#pragma unroll
        for (int k = 0; k < H; k++) {
            float a = sin_[w][k];
            float2 wk = Ws[k][t];
            a0 = fmaf(a, wk.x, a0);
            a1 = fmaf(a, wk.y, a1);
        }
        if (has_res) {
            a0 += g_h[base + t];
            a1 += g_h[base + t + 32];
        }
        g_h[base + t] = a0;
        g_h[base + t + 32] = a1;

        if (ln_layer >= 0) {
            // LayerNorm over the 64 values (2 per lane) + ReLU -> next msg
            float s = a0 + a1;
#pragma unroll
            for (int o = 16; o > 0; o >>= 1) s += __shfl_xor_sync(0xffffffffu, s, o);
            float mu = s * (1.f / 64.f);
            float dd0 = a0 - mu, dd1 = a1 - mu;
            float q = dd0 * dd0 + dd1 * dd1;
#pragma unroll
            for (int o = 16; o > 0; o >>= 1) q += __shfl_xor_sync(0xffffffffu, q, o);
            float var = q * (1.f / 64.f);
            float r = rsqrtf(var + LN_EPS);
            float m0 = fmaxf(fmaf(dd0 * r, g0, be0), 0.f);
            float m1 = fmaxf(fmaf(dd1 * r, g1, be1), 0.f);
            g_msg[base + t] = m0;
            g_msg[base + t + 32] = m1;
        }
        __syncwarp();
    }
}

// ---------------- prediction head: out = h @ pred_W + pred_b -----------------
__global__ __launch_bounds__(256) void pred_kernel(const float* __restrict__ W,
                                                   const float* __restrict__ b,
                                                   float* __restrict__ out) {
    __shared__ __align__(16) float Ws[H * OUT_DIM + 32];  // padded (unguarded 4th-column read)
    __shared__ __align__(16) float sin_[8][H];
    int t = threadIdx.x & 31;
    int w = threadIdx.x >> 5;

    for (int i = threadIdx.x; i < H * OUT_DIM; i += blockDim.x) Ws[i] = W[i];
    __syncthreads();

    float b0 = b[t], b1 = b[t + 32], b2 = b[t + 64];
    float b3 = (t < 16) ? b[t + 96] : 0.f;
    int nwarps = gridDim.x * (blockDim.x >> 5);
    for (int row = blockIdx.x * 8 + w; row < N_NODES; row += nwarps) {
        int base = row * H;
        sin_[w][t] = g_h[base + t];
        sin_[w][t + 32] = g_h[base + t + 32];
        __syncwarp();
        float a0 = b0, a1 = b1, a2 = b2, a3 = b3;
#pragma unroll
        for (int k = 0; k < H; k++) {
            float a = sin_[w][k];
            const float* wr = &Ws[k * OUT_DIM];
            a0 = fmaf(a, wr[t], a0);
            a1 = fmaf(a, wr[t + 32], a1);
            a2 = fmaf(a, wr[t + 64], a2);
            a3 = fmaf(a, wr[t + 96], a3);   // padded read for t>=16, discarded
        }
        float* orow = out + (size_t)row * OUT_DIM;
        orow[t] = a0;
        orow[t + 32] = a1;
        orow[t + 64] = a2;
        if (t < 16) orow[t + 96] = a3;
        __syncwarp();
    }
}

// ---------------- host launch -----------------------------------------------
extern "C" void kernel_launch(void* const* d_in, const int* in_sizes, int n_in,
                              void* d_out, int out_size) {
    const float* x      = (const float*)d_in[0];
    const void*  ei     = d_in[1];
    const float* enc_W  = (const float*)d_in[2];
    const float* enc_b  = (const float*)d_in[3];
    const float* ln_g   = (const float*)d_in[4];
    const float* ln_b   = (const float*)d_in[5];
    const float* mlp_W  = (const float*)d_in[6];
    const float* mlp_b  = (const float*)d_in[7];
    const float* pred_W = (const float*)d_in[8];
    const float* pred_b = (const float*)d_in[9];
    float*       out    = (float*)d_out;

    // dtype detection + CSR build (edge structure fixed across layers)
    detect_kernel<<<1, 32>>>(ei);
    zero_kernel<<<(N_NODES + 255) / 256, 256>>>();
    count_kernel<<<(N_EDGES + 255) / 256, 256>>>(ei);
    scan_kernel<<<1, 1024>>>();
    scatter_kernel<<<(N_EDGES + 255) / 256, 256>>>(ei);
    sort_kernel<<<(N_NODES + 255) / 256, 256>>>();

    // encoder
    enc_kernel<<<592, 256>>>(x, enc_W, enc_b);

    // 14 GENConv layers
    for (int l = 0; l < L_LAYERS; l++) {
        agg_kernel<<<(N_NODES + 15) / 16, 512>>>();
        int use_msg = (l >= 1);
        int has_res = (l >= 1);
        int ln_layer = (l <= L_LAYERS - 2) ? l : -1;
        lin_kernel<<<592, 256>>>(mlp_W + (size_t)l * H * H, mlp_b + (size_t)l * H,
                                 use_msg, has_res, ln_layer, ln_g, ln_b);
    }

    // prediction head
    pred_kernel<<<592, 256>>>(pred_W, pred_b, out);
}

// round 14
// speedup vs baseline: 1.2391x; 1.2391x over previous
#include <cuda_runtime.h>
#include <cuda_bf16.h>
#include <cuda_fp16.h>
#include <math.h>

#define N_NODES 50000
#define N_EDGES 800000
#define H       64
#define L_LAYERS 14
#define IN_DIM  128
#define OUT_DIM 112
#define MSG_EPS 1e-7f
#define LN_EPS  1e-5f
#define SCAN_B  1024
#define SCAN_NB ((N_NODES + SCAN_B - 1) / SCAN_B)   // 49

// ---------------- scratch (device globals: no allocations allowed) ----------
__device__ float  g_h[N_NODES * H];          // node state (residual carry)
__device__ float  g_msgf[2][N_NODES * H];    // fp32 msg (own-row lin input), double-buffered
__device__ __half g_msgh[2][N_NODES * H];    // fp16 msg (edge gather source), double-buffered
__device__ int    g_rowptr[N_NODES + 1];
__device__ int    g_cursor[N_NODES];
__device__ int    g_csrc[N_EDGES];
__device__ int    g_blocksum[SCAN_NB];
__device__ int    g_blockoff[SCAN_NB];
__device__ int    g_is32;                    // 1 if edge_index is int32, 0 if int64

// ---------------- dtype detection -------------------------------------------
// Sample the first 1024 entries under the int64 interpretation (byte offsets
// < 8KB: in-bounds for either dtype). If any lies outside [0, N_NODES) the
// buffer must be int32 (P[all 1024 int32-pairs have hi-word 0] ~ 0).
__global__ void detect_kernel(const void* __restrict__ ei) {
    if (threadIdx.x == 0 && blockIdx.x == 0) {
        const long long* p = (const long long*)ei;
        int bad = 0;
        for (int i = 0; i < 1024; i++) {
            long long v = p[i];
            if (v < 0 || v >= N_NODES) { bad = 1; break; }
        }
        g_is32 = bad;
    }
}

__device__ __forceinline__ int load_idx(const void* ei, int i, int is32) {
    int v = is32 ? ((const int*)ei)[i] : (int)((const long long*)ei)[i];
    v = v < 0 ? 0 : (v >= N_NODES ? N_NODES - 1 : v);   // defensive clamp
    return v;
}

// ---------------- CSR build --------------------------------------------------
__global__ void zero_kernel() {
    int i = blockIdx.x * blockDim.x + threadIdx.x;
    if (i < N_NODES) g_cursor[i] = 0;
}

__global__ void count_kernel(const void* __restrict__ ei) {
    int e = blockIdx.x * blockDim.x + threadIdx.x;
    if (e < N_EDGES) {
        int is32 = g_is32;
        int d = load_idx(ei, N_EDGES + e, is32);
        atomicAdd(&g_cursor[d], 1);
    }
}

// multi-block scan, stage A: per-block inclusive scan of counts
__global__ __launch_bounds__(SCAN_B) void scanA_kernel() {
    __shared__ int sm[SCAN_B];
    int t = threadIdx.x, b = blockIdx.x;
    int i = b * SCAN_B + t;
    int c = (i < N_NODES) ? g_cursor[i] : 0;
    sm[t] = c;
    __syncthreads();
    for (int o = 1; o < SCAN_B; o <<= 1) {
        int v = (t >= o) ? sm[t - o] : 0;
        __syncthreads();
        sm[t] += v;
        __syncthreads();
    }
    if (i < N_NODES) g_rowptr[i] = sm[t] - c;   // block-local exclusive
    if (t == SCAN_B - 1) g_blocksum[b] = sm[t];
}

// stage B: serial scan of 49 block sums (tiny)
__global__ void scanB_kernel() {
    if (threadIdx.x == 0 && blockIdx.x == 0) {
        int run = 0;
        for (int b = 0; b < SCAN_NB; b++) {
            g_blockoff[b] = run;
            run += g_blocksum[b];
        }
        g_rowptr[N_NODES] = run;
    }
}

// stage C: add block offsets; init scatter cursors
__global__ __launch_bounds__(SCAN_B) void scanC_kernel() {
    int b = blockIdx.x;
    int i = b * SCAN_B + threadIdx.x;
    if (i < N_NODES) {
        int r = g_rowptr[i] + g_blockoff[b];
        g_rowptr[i] = r;
        g_cursor[i] = r;
    }
}

__global__ void scatter_kernel(const void* __restrict__ ei) {
    int e = blockIdx.x * blockDim.x + threadIdx.x;
    if (e < N_EDGES) {
        int is32 = g_is32;
        int s = load_idx(ei, e, is32);
        int d = load_idx(ei, N_EDGES + e, is32);
        int p = atomicAdd(&g_cursor[d], 1);
        g_csrc[p] = s;
    }
}

// per-row insertion sort: deterministic CSR -> deterministic fp sum order
__global__ void sort_kernel() {
    int n = blockIdx.x * blockDim.x + threadIdx.x;
    if (n >= N_NODES) return;
    int s = g_rowptr[n], e = g_rowptr[n + 1];
    for (int i = s + 1; i < e; i++) {
        int v = g_csrc[i];
        int j = i - 1;
        while (j >= s && g_csrc[j] > v) { g_csrc[j + 1] = g_csrc[j]; j--; }
        g_csrc[j + 1] = v;
    }
}

// ---------------- encoder: h = x @ enc_W + enc_b ; msg[0] = relu(h) ----------
__global__ __launch_bounds__(256) void enc_kernel(const float* __restrict__ x,
                                                  const float* __restrict__ W,
                                                  const float* __restrict__ b) {
    __shared__ __align__(16) float2 Ws[IN_DIM][H / 2];
    __shared__ __align__(16) float  sin_[8][IN_DIM];
    int t = threadIdx.x & 31;
    int w = threadIdx.x >> 5;

    for (int i = threadIdx.x; i < IN_DIM * (H / 2); i += blockDim.x) {
        int k = i >> 5, tt = i & 31;
        Ws[k][tt] = make_float2(W[k * H + tt], W[k * H + tt + 32]);
    }
    __syncthreads();

    float bb0 = b[t], bb1 = b[t + 32];
    int nwarps = gridDim.x * (blockDim.x >> 5);
    for (int row = blockIdx.x * 8 + w; row < N_NODES; row += nwarps) {
        const float4* xr = (const float4*)(x + (size_t)row * IN_DIM);
        ((float4*)sin_[w])[t] = xr[t];
        __syncwarp();
        float a0 = bb0, a1 = bb1;
#pragma unroll 16
        for (int k = 0; k < IN_DIM; k++) {
            float a = sin_[w][k];
            float2 wk = Ws[k][t];
            a0 = fmaf(a, wk.x, a0);
            a1 = fmaf(a, wk.y, a1);
        }
        int base = row * H;
        g_h[base + t] = a0;
        g_h[base + t + 32] = a1;
        float m0 = fmaxf(a0, 0.f), m1 = fmaxf(a1, 0.f);
        g_msgf[0][base + t] = m0;
        g_msgf[0][base + t + 32] = m1;
        g_msgh[0][base + t] = __float2half(m0);
        g_msgh[0][base + t + 32] = __float2half(m1);
        __syncwarp();
    }
}

// ---------------- fused GENConv layer ----------------------------------------
// agg (softmax, no-max-pass, fp16 gather) + linear + bias + residual + next LN+ReLU.
// Double-buffered messages: read buffer p, write buffer p^1 (no intra-launch race).
// Warp per node. Gather: lane t owns features (2t,2t+1) via one half2.
// GEMM: lane t owns outputs (t, t+32); inputs staged to per-warp smem.
__global__ __launch_bounds__(512) void layer_kernel(const float* __restrict__ W,
                                                    const float* __restrict__ bias,
                                                    int use_lin_h, int has_res,
                                                    int ln_layer,
                                                    const float* __restrict__ ln_g,
                                                    const float* __restrict__ ln_b,
                                                    int p) {
    __shared__ __align__(16) float2 Ws[H][H / 2];
    __shared__ __align__(16) float  sin_[16][H];
    int t = threadIdx.x & 31;
    int w = threadIdx.x >> 5;

    for (int i = threadIdx.x; i < H * (H / 2); i += blockDim.x) {
        int k = i >> 5, tt = i & 31;
        Ws[k][tt] = make_float2(W[k * H + tt], W[k * H + tt + 32]);
    }
    __syncthreads();

    float bb0 = bias[t], bb1 = bias[t + 32];
    float g0 = 1.f, g1 = 1.f, be0 = 0.f, be1 = 0.f;
    if (ln_layer >= 0) {
        g0 = ln_g[ln_layer * H + t];      g1 = ln_g[ln_layer * H + t + 32];
        be0 = ln_b[ln_layer * H + t];     be1 = ln_b[ln_layer * H + t + 32];
    }

    const __half2* mh = (const __half2*)g_msgh[p];     // gather source (32 half2 per row)
    const float*   mf = use_lin_h ? g_h : g_msgf[p];   // row-local linear input
    int q = p ^ 1;
    int nwarps = gridDim.x * 16;

    for (int node = blockIdx.x * 16 + w; node < N_NODES; node += nwarps) {
        int s = g_rowptr[node], e = g_rowptr[node + 1];
        float d0 = 0.f, d1 = 0.f, n0 = 0.f, n1 = 0.f;
#define PROC(hv) { float2 pv = __half22float2(hv); \
                   float vx = pv.x + MSG_EPS; float vy = pv.y + MSG_EPS; \
                   float wx = __expf(vx); float wy = __expf(vy); \
                   d0 += wx; n0 = fmaf(vx, wx, n0); \
                   d1 += wy; n1 = fmaf(vy, wy, n1); }
        int i = s;
        for (; i + 8 <= e; i += 8) {
            int s0 = __ldg(&g_csrc[i]);
            int s1 = __ldg(&g_csrc[i + 1]);
            int s2 = __ldg(&g_csrc[i + 2]);
            int s3 = __ldg(&g_csrc[i + 3]);
            int s4 = __ldg(&g_csrc[i + 4]);
            int s5 = __ldg(&g_csrc[i + 5]);
            int s6 = __ldg(&g_csrc[i + 6]);
            int s7 = __ldg(&g_csrc[i + 7]);
            __half2 h0 = __ldg(&mh[s0 * 32 + t]);
            __half2 h1 = __ldg(&mh[s1 * 32 + t]);
            __half2 h2 = __ldg(&mh[s2 * 32 + t]);
            __half2 h3 = __ldg(&mh[s3 * 32 + t]);
            __half2 h4 = __ldg(&mh[s4 * 32 + t]);
            __half2 h5 = __ldg(&mh[s5 * 32 + t]);
            __half2 h6 = __ldg(&mh[s6 * 32 + t]);
            __half2 h7 = __ldg(&mh[s7 * 32 + t]);
            PROC(h0); PROC(h1); PROC(h2); PROC(h3);
            PROC(h4); PROC(h5); PROC(h6); PROC(h7);
        }
        for (; i + 4 <= e; i += 4) {
            int s0 = __ldg(&g_csrc[i]);
            int s1 = __ldg(&g_csrc[i + 1]);
            int s2 = __ldg(&g_csrc[i + 2]);
            int s3 = __ldg(&g_csrc[i + 3]);
            __half2 h0 = __ldg(&mh[s0 * 32 + t]);
            __half2 h1 = __ldg(&mh[s1 * 32 + t]);
            __half2 h2 = __ldg(&mh[s2 * 32 + t]);
            __half2 h3 = __ldg(&mh[s3 * 32 + t]);
            PROC(h0); PROC(h1); PROC(h2); PROC(h3);
        }
        for (; i < e; i++) {
            int s0 = __ldg(&g_csrc[i]);
            __half2 h0 = __ldg(&mh[s0 * 32 + t]);
            PROC(h0);
        }
#undef PROC
        float agg0 = (e > s) ? n0 / d0 : 0.f;
        float agg1 = (e > s) ? n1 / d1 : 0.f;

        int base = node * H;
        float2 lf = *(const float2*)&mf[base + 2 * t];
        sin_[w][2 * t]     = lf.x + agg0;
        sin_[w][2 * t + 1] = lf.y + agg1;
        __syncwarp();

        float a0 = bb0, a1 = bb1;
#pragma unroll
        for (int k = 0; k < H; k++) {
            float a = sin_[w][k];
            float2 wk = Ws[k][t];
            a0 = fmaf(a, wk.x, a0);
            a1 = fmaf(a, wk.y, a1);
        }
        if (has_res) {
            a0 += g_h[base + t];
            a1 += g_h[base + t + 32];
        }
        g_h[base + t] = a0;
        g_h[base + t + 32] = a1;

        if (ln_layer >= 0) {
            float sum = a0 + a1;
#pragma unroll
            for (int o = 16; o > 0; o >>= 1) sum += __shfl_xor_sync(0xffffffffu, sum, o);
            float mu = sum * (1.f / 64.f);
            float dd0 = a0 - mu, dd1 = a1 - mu;
            float qq = dd0 * dd0 + dd1 * dd1;
#pragma unroll
            for (int o = 16; o > 0; o >>= 1) qq += __shfl_xor_sync(0xffffffffu, qq, o);
            float var = qq * (1.f / 64.f);
            float r = rsqrtf(var + LN_EPS);
            float m0 = fmaxf(fmaf(dd0 * r, g0, be0), 0.f);
            float m1 = fmaxf(fmaf(dd1 * r, g1, be1), 0.f);
            g_msgf[q][base + t] = m0;
            g_msgf[q][base + t + 32] = m1;
            g_msgh[q][base + t] = __float2half(m0);
            g_msgh[q][base + t + 32] = __float2half(m1);
        }
        __syncwarp();
    }
}

// ---------------- prediction head: out = h @ pred_W + pred_b -----------------
__global__ __launch_bounds__(256) void pred_kernel(const float* __restrict__ W,
                                                   const float* __restrict__ b,
                                                   float* __restrict__ out) {
    __shared__ __align__(16) float Ws[H * OUT_DIM + 32];  // padded
    __shared__ __align__(16) float sin_[8][H];
    int t = threadIdx.x & 31;
    int w = threadIdx.x >> 5;

    for (int i = threadIdx.x; i < H * OUT_DIM; i += blockDim.x) Ws[i] = W[i];
    __syncthreads();

    float b0 = b[t], b1 = b[t + 32], b2 = b[t + 64];
    float b3 = (t < 16) ? b[t + 96] : 0.f;
    int nwarps = gridDim.x * (blockDim.x >> 5);
    for (int row = blockIdx.x * 8 + w; row < N_NODES; row += nwarps) {
        int base = row * H;
        sin_[w][t] = g_h[base + t];
        sin_[w][t + 32] = g_h[base + t + 32];
        __syncwarp();
        float a0 = b0, a1 = b1, a2 = b2, a3 = b3;
#pragma unroll
        for (int k = 0; k < H; k++) {
            float a = sin_[w][k];
            const float* wr = &Ws[k * OUT_DIM];
            a0 = fmaf(a, wr[t], a0);
            a1 = fmaf(a, wr[t + 32], a1);
            a2 = fmaf(a, wr[t + 64], a2);
            a3 = fmaf(a, wr[t + 96], a3);   // padded read for t>=16, discarded
        }
        float* orow = out + (size_t)row * OUT_DIM;
        orow[t] = a0;
        orow[t + 32] = a1;
        orow[t + 64] = a2;
        if (t < 16) orow[t + 96] = a3;
        __syncwarp();
    }
}

// ---------------- host launch -----------------------------------------------
extern "C" void kernel_launch(void* const* d_in, const int* in_sizes, int n_in,
                              void* d_out, int out_size) {
    const float* x      = (const float*)d_in[0];
    const void*  ei     = d_in[1];
    const float* enc_W  = (const float*)d_in[2];
    const float* enc_b  = (const float*)d_in[3];
    const float* ln_g   = (const float*)d_in[4];
    const float* ln_b   = (const float*)d_in[5];
    const float* mlp_W  = (const float*)d_in[6];
    const float* mlp_b  = (const float*)d_in[7];
    const float* pred_W = (const float*)d_in[8];
    const float* pred_b = (const float*)d_in[9];
    float*       out    = (float*)d_out;

    // dtype detection + CSR build (edge structure fixed across layers)
    detect_kernel<<<1, 32>>>(ei);
    zero_kernel<<<(N_NODES + 255) / 256, 256>>>();
    count_kernel<<<(N_EDGES + 255) / 256, 256>>>(ei);
    scanA_kernel<<<SCAN_NB, SCAN_B>>>();
    scanB_kernel<<<1, 1>>>();
    scanC_kernel<<<SCAN_NB, SCAN_B>>>();
    scatter_kernel<<<(N_EDGES + 255) / 256, 256>>>(ei);
    sort_kernel<<<(N_NODES + 255) / 256, 256>>>();

    // encoder -> g_h, msg buffer 0
    enc_kernel<<<592, 256>>>(x, enc_W, enc_b);

    // 14 fused GENConv layers (ping-pong message buffers)
    for (int l = 0; l < L_LAYERS; l++) {
        int parity   = l & 1;
        int use_lin_h = (l == 0);
        int has_res  = (l >= 1);
        int ln_layer = (l <= L_LAYERS - 2) ? l : -1;
        layer_kernel<<<592, 512>>>(mlp_W + (size_t)l * H * H, mlp_b + (size_t)l * H,
                                   use_lin_h, has_res, ln_layer, ln_g, ln_b, parity);
    }

    // prediction head
    pred_kernel<<<592, 256>>>(pred_W, pred_b, out);
}